// round 1
// baseline (speedup 1.0000x reference)
#include <cuda_runtime.h>
#include <math.h>

// Problem constants
#define EMB   768
#define NH    8
#define HD    96
#define NB    4
#define NSEQ  2048
#define BHTOT 32            // NB*NH
#define MROWS 8192          // NB*NSEQ

// ---------------- scratch (device globals; no allocation allowed) ----------
__device__ float g_q [BHTOT * NSEQ * HD];               // [BH, N, d]
__device__ float g_k [BHTOT * NSEQ * HD];
__device__ float g_v [BHTOT * NSEQ * HD];
__device__ float g_s [(size_t)BHTOT * NSEQ * NSEQ];     // [BH, N, N] (537 MB)
__device__ float g_ao[(size_t)MROWS * EMB];             // [B*N, E]

// ---------------- generic tiled SGEMM --------------------------------------
// C = alpha * A @ op(B) + bias
//   TRANS_B=true : B is [N,K] row-major (computes A @ B^T)  -> "NT"
//   TRANS_B=false: B is [K,N] row-major (computes A @ B)    -> "NN"
// MODE 0: plain output  C[z*strideCz + m*ldc + n]
// MODE 1: QKV scatter   out[((b*NH+h)*NSEQ + n_seq)*HD + dd]   (M=MROWS, N=EMB)
// MODE 2: head merge    out[(b*NSEQ+m)*EMB + h*HD + n]         (z = b*NH+h, N=HD)
template<int MODE, bool TRANS_B>
__global__ __launch_bounds__(256)
void gemm_kernel(const float* __restrict__ A, const float* __restrict__ B,
                 const float* __restrict__ bias, float* __restrict__ C,
                 int M, int N, int K, float alpha,
                 long strideAz, long strideBz, long strideCz, int ldc)
{
    const int BM = 128, BN = 128, BK = 8;
    __shared__ float As[BK][BM];
    __shared__ float Bs[BK][BN];

    const int z = blockIdx.z;
    A += (long)z * strideAz;
    B += (long)z * strideBz;

    const int m0 = blockIdx.y * BM;
    const int n0 = blockIdx.x * BN;
    const int t  = threadIdx.x;

    float acc[8][8];
#pragma unroll
    for (int i = 0; i < 8; i++)
#pragma unroll
        for (int j = 0; j < 8; j++) acc[i][j] = 0.f;

    // load-index mapping
    const int a_row  = t >> 1;            // 0..127 (m within tile)
    const int a_col  = (t & 1) * 4;       // k base (0 or 4)
    const int bT_row = t >> 1;            // n within tile (TRANS_B)
    const int bT_col = (t & 1) * 4;       // k base
    const int bN_row = t >> 5;            // k within tile (NN)
    const int bN_col = (t & 31) * 4;      // n base

    const int tm = (t >> 4) * 8;          // this thread's 8 output rows
    const int tn = (t & 15) * 8;          // this thread's 8 output cols

    for (int k0 = 0; k0 < K; k0 += BK) {
        // ---- stage A tile (transposed into shared: As[k][m]) ----
#pragma unroll
        for (int i = 0; i < 4; i++) {
            int gm = m0 + a_row, gk = k0 + a_col + i;
            As[a_col + i][a_row] = (gm < M && gk < K) ? A[(long)gm * K + gk] : 0.f;
        }
        // ---- stage B tile (Bs[k][n]) ----
        if (TRANS_B) {
#pragma unroll
            for (int i = 0; i < 4; i++) {
                int gn = n0 + bT_row, gk = k0 + bT_col + i;
                Bs[bT_col + i][bT_row] = (gn < N && gk < K) ? B[(long)gn * K + gk] : 0.f;
            }
        } else {
#pragma unroll
            for (int i = 0; i < 4; i++) {
                int gk = k0 + bN_row, gn = n0 + bN_col + i;
                Bs[bN_row][bN_col + i] = (gk < K && gn < N) ? B[(long)gk * N + gn] : 0.f;
            }
        }
        __syncthreads();

#pragma unroll
        for (int k = 0; k < BK; k++) {
            float4 a0 = *reinterpret_cast<const float4*>(&As[k][tm]);
            float4 a1 = *reinterpret_cast<const float4*>(&As[k][tm + 4]);
            float4 b0 = *reinterpret_cast<const float4*>(&Bs[k][tn]);
            float4 b1 = *reinterpret_cast<const float4*>(&Bs[k][tn + 4]);
            float fa[8] = {a0.x, a0.y, a0.z, a0.w, a1.x, a1.y, a1.z, a1.w};
            float fb[8] = {b0.x, b0.y, b0.z, b0.w, b1.x, b1.y, b1.z, b1.w};
#pragma unroll
            for (int i = 0; i < 8; i++)
#pragma unroll
                for (int j = 0; j < 8; j++)
                    acc[i][j] = fmaf(fa[i], fb[j], acc[i][j]);
        }
        __syncthreads();
    }

    // ---- epilogue ----
#pragma unroll
    for (int i = 0; i < 8; i++) {
        int gm = m0 + tm + i;
        if (gm >= M) continue;
#pragma unroll
        for (int j = 0; j < 8; j++) {
            int gn = n0 + tn + j;
            if (gn >= N) continue;
            float vv = acc[i][j] * alpha;
            if (bias) vv += bias[gn];
            if (MODE == 0) {
                C[(long)z * strideCz + (long)gm * ldc + gn] = vv;
            } else if (MODE == 1) {
                int b  = gm / NSEQ, nseq = gm % NSEQ;
                int h  = gn / HD,   dd   = gn % HD;
                C[((long)(b * NH + h) * NSEQ + nseq) * HD + dd] = vv;
            } else { // MODE == 2
                int b = z / NH, h = z % NH;
                C[((long)(b * NSEQ + gm)) * EMB + h * HD + gn] = vv;
            }
        }
    }
}

// ---------------- row softmax (in place) ------------------------------------
__global__ __launch_bounds__(256)
void softmax_rows(float* __restrict__ S, int ncols)
{
    long row = blockIdx.x;
    float* p = S + row * (long)ncols;
    const int t = threadIdx.x;
    __shared__ float red[8];

    // row max
    float m = -3.0e38f;
    for (int i = t; i < ncols; i += 256) m = fmaxf(m, p[i]);
#pragma unroll
    for (int o = 16; o; o >>= 1) m = fmaxf(m, __shfl_xor_sync(0xFFFFFFFFu, m, o));
    if ((t & 31) == 0) red[t >> 5] = m;
    __syncthreads();
    float rowmax = red[0];
#pragma unroll
    for (int w = 1; w < 8; w++) rowmax = fmaxf(rowmax, red[w]);
    __syncthreads();

    // exp + sum
    float s = 0.f;
    for (int i = t; i < ncols; i += 256) {
        float e = __expf(p[i] - rowmax);
        p[i] = e;
        s += e;
    }
#pragma unroll
    for (int o = 16; o; o >>= 1) s += __shfl_xor_sync(0xFFFFFFFFu, s, o);
    if ((t & 31) == 0) red[t >> 5] = s;
    __syncthreads();
    float total = red[0];
#pragma unroll
    for (int w = 1; w < 8; w++) total += red[w];
    float inv = 1.0f / total;

    for (int i = t; i < ncols; i += 256) p[i] *= inv;
}

// ---------------- launcher ---------------------------------------------------
extern "C" void kernel_launch(void* const* d_in, const int* in_sizes, int n_in,
                              void* d_out, int out_size)
{
    const float* x  = (const float*)d_in[0];
    const float* Wq = (const float*)d_in[1];
    const float* bq = (const float*)d_in[2];
    const float* Wk = (const float*)d_in[3];
    const float* bk = (const float*)d_in[4];
    const float* Wv = (const float*)d_in[5];
    const float* bv = (const float*)d_in[6];
    const float* Wo = (const float*)d_in[7];
    const float* bo = (const float*)d_in[8];
    float* out = (float*)d_out;

    float *q, *k, *v, *s, *ao;
    cudaGetSymbolAddress((void**)&q,  g_q);
    cudaGetSymbolAddress((void**)&k,  g_k);
    cudaGetSymbolAddress((void**)&v,  g_v);
    cudaGetSymbolAddress((void**)&s,  g_s);
    cudaGetSymbolAddress((void**)&ao, g_ao);

    dim3 blk(256);

    // 1) Q/K/V projections: [8192,768] @ W^T + b, scattered to [BH,N,d]
    dim3 gproj((EMB + 127) / 128, (MROWS + 127) / 128, 1);
    gemm_kernel<1, true><<<gproj, blk>>>(x, Wq, bq, q, MROWS, EMB, EMB, 1.f, 0, 0, 0, 0);
    gemm_kernel<1, true><<<gproj, blk>>>(x, Wk, bk, k, MROWS, EMB, EMB, 1.f, 0, 0, 0, 0);
    gemm_kernel<1, true><<<gproj, blk>>>(x, Wv, bv, v, MROWS, EMB, EMB, 1.f, 0, 0, 0, 0);

    // 2) S = (1/sqrt(d)) * Q @ K^T, batched over BH
    const float scale = 0.10206207261596577f;  // 1/sqrt(96)
    dim3 gS(NSEQ / 128, NSEQ / 128, BHTOT);
    gemm_kernel<0, true><<<gS, blk>>>(q, k, nullptr, s, NSEQ, NSEQ, HD, scale,
                                      (long)NSEQ * HD, (long)NSEQ * HD,
                                      (long)NSEQ * NSEQ, NSEQ);

    // 3) softmax over rows of S
    softmax_rows<<<BHTOT * NSEQ, blk>>>(s, NSEQ);

    // 4) O = P @ V, merged back to [B*N, E]
    dim3 gO(1, NSEQ / 128, BHTOT);
    gemm_kernel<2, false><<<gO, blk>>>(s, v, nullptr, ao, NSEQ, HD, NSEQ, 1.f,
                                       (long)NSEQ * NSEQ, (long)NSEQ * HD, 0, 0);

    // 5) out = AO @ Wo^T + bo
    dim3 gout((EMB + 127) / 128, (MROWS + 127) / 128, 1);
    gemm_kernel<0, true><<<gout, blk>>>(ao, Wo, bo, out, MROWS, EMB, EMB, 1.f,
                                        0, 0, 0, EMB);
}

// round 3
// speedup vs baseline: 3.6659x; 3.6659x over previous
#include <cuda_runtime.h>
#include <cuda_bf16.h>
#include <cstdint>

#define EMB  768
#define NH   8
#define HD   96
#define NB   4
#define NSEQ 2048
#define BH   32            // NB*NH
#define MR   8192          // NB*NSEQ
#define K3   2304          // 3*EMB   (split-interleaved K)
#define KQK  320           // 3*HD=288 padded to 320 (5 chunks of 64)
#define KPV  6144          // 3*NSEQ

// ---------------- scratch (device globals; no allocation allowed) -----------
__device__ __nv_bfloat16 g_x3 [(long)MR * K3];
__device__ __nv_bfloat16 g_wq3[(long)EMB * K3];
__device__ __nv_bfloat16 g_wk3[(long)EMB * K3];
__device__ __nv_bfloat16 g_wv3[(long)EMB * K3];
__device__ __nv_bfloat16 g_wo3[(long)EMB * K3];
__device__ __nv_bfloat16 g_q3 [(long)BH * NSEQ * KQK];
__device__ __nv_bfloat16 g_k3 [(long)BH * NSEQ * KQK];
__device__ __nv_bfloat16 g_v3 [(long)BH * HD * KPV];
__device__ float         g_S  [(long)BH * NSEQ * NSEQ];   // 537 MB
__device__ __nv_bfloat16 g_p3 [(long)BH * NSEQ * KPV];    // 805 MB
__device__ __nv_bfloat16 g_ao3[(long)MR * K3];

// ---------------- helpers ----------------------------------------------------
#define SW128(o) ((o) ^ (((o) >> 3) & 0x70))

__device__ __forceinline__ uint32_t smem_u32(const void* p) {
    uint32_t a;
    asm("{ .reg .u64 t; cvta.to.shared.u64 t, %1; cvt.u32.u64 %0, t; }" : "=r"(a) : "l"(p));
    return a;
}
__device__ __forceinline__ void cp16(uint32_t dst, const void* src, uint32_t sz) {
    asm volatile("cp.async.cg.shared.global [%0], [%1], 16, %2;"
                 :: "r"(dst), "l"(src), "r"(sz) : "memory");
}

// ---------------- epilogue element store -------------------------------------
// MODE: 0=Qproj 1=Kproj 2=Vproj 3=Score 4=PV 5=Out
template<int MODE>
__device__ __forceinline__ void store_elem(void* out, const float* bias, int z,
                                           long m, long n, float v)
{
    if (MODE == 3) {
        ((float*)out)[((long)z * NSEQ + m) * NSEQ + n] = v;
    } else if (MODE == 5) {
        ((float*)out)[m * (long)EMB + n] = v + bias[n];
    } else if (MODE == 4) {
        const int bb = z >> 3, h = z & 7;
        const long base = ((long)(bb * NSEQ + m)) * K3 + 3L * (h * HD + (int)n);
        __nv_bfloat16 hi = __float2bfloat16(v);
        __nv_bfloat16 lo = __float2bfloat16(v - __bfloat162float(hi));
        __nv_bfloat16* o = (__nv_bfloat16*)out;
        o[base] = hi; o[base + 1] = hi; o[base + 2] = lo;     // A pattern
    } else {
        v += bias[n];
        if (MODE == 0) v *= 0.10206207261596577f;             // 1/sqrt(96)
        const int h = (int)n / HD, dd = (int)n % HD;
        const int bb = (int)(m / NSEQ), ns = (int)(m % NSEQ);
        const int bh = bb * NH + h;
        __nv_bfloat16 hi = __float2bfloat16(v);
        __nv_bfloat16 lo = __float2bfloat16(v - __bfloat162float(hi));
        __nv_bfloat16* o = (__nv_bfloat16*)out;
        if (MODE == 2) {                                      // V transposed, B pattern
            const long base = ((long)bh * HD + dd) * KPV + 3L * ns;
            o[base] = hi; o[base + 1] = lo; o[base + 2] = hi;
        } else {
            const long base = ((long)bh * NSEQ + ns) * KQK + 3 * dd;
            if (MODE == 0) { o[base] = hi; o[base + 1] = hi; o[base + 2] = lo; } // A pat
            else           { o[base] = hi; o[base + 1] = lo; o[base + 2] = hi; } // B pat
        }
    }
}

// ---------------- HMMA (mma.sync) GEMM ---------------------------------------
// D[128 x 128] = A_tile @ B_tile^T over Kc chunks of 64 bf16 (K split-interleaved).
// A row-major [M, lda]; B row-major [Nrows, ldb] (i.e. computes A @ B^T).
#define SMEM_TOTAL 65536   // 2 x (A 16KB + B 16KB)

template<int MODE>
__global__ __launch_bounds__(256)
void mma_gemm(const __nv_bfloat16* __restrict__ A, const __nv_bfloat16* __restrict__ B,
              const float* __restrict__ bias, void* __restrict__ out,
              int lda, int ldb, int Kc, int Brows, int Ncols,
              long strideAz, long strideBz)
{
    extern __shared__ char smem[];
    const uint32_t sb = smem_u32(smem);
    const int tid = threadIdx.x;
    const int wid = tid >> 5, lane = tid & 31;
    const int z = blockIdx.z;
    const long m0 = (long)blockIdx.y * 128;
    const long n0 = (long)blockIdx.x * 128;
    A += (long)z * strideAz + m0 * lda;
    B += (long)z * strideBz + n0 * ldb;

    // warp tile: 2 warps over M (64 rows each), 4 warps over N (32 cols each)
    const int wm = (wid & 1) * 64;
    const int wn = (wid >> 1) * 32;

    float acc[4][4][4];
#pragma unroll
    for (int i = 0; i < 4; i++)
#pragma unroll
        for (int j = 0; j < 4; j++)
#pragma unroll
            for (int c = 0; c < 4; c++) acc[i][j][c] = 0.f;

    // ldmatrix per-thread source coordinates
    const int l16   = lane & 15;
    const int aRow  = wm + l16;                 // + i*16
    const int aColB = (lane >> 4) * 16;         // + ks*32
    const int bRow  = wn + (l16 & 7);           // + j*8
    const int bColB = ((l16 >> 3) & 1) * 16;    // + ks*32

    // ---- staging ----
    auto stage = [&](int c) {
        const long k0 = (long)c * 64;
        const uint32_t bufA = sb + (uint32_t)(c & 1) * 32768u;
        const uint32_t bufB = bufA + 16384u;
#pragma unroll
        for (int i = 0; i < 4; i++) {
            int v = tid + i * 256;
            int row = v >> 3, c16 = v & 7;
            uint32_t off = SW128((uint32_t)(row * 128 + c16 * 16));
            cp16(bufA + off, A + (long)row * lda + k0 + c16 * 8, 16u);
            int brow = row < Brows ? row : (Brows - 1);
            cp16(bufB + off, B + (long)brow * ldb + k0 + c16 * 8,
                 (row < Brows) ? 16u : 0u);
        }
        asm volatile("cp.async.commit_group;" ::: "memory");
    };

    stage(0);
    for (int c = 0; c < Kc; c++) {
        if (c + 1 < Kc) {
            stage(c + 1);
            asm volatile("cp.async.wait_group 1;" ::: "memory");
        } else {
            asm volatile("cp.async.wait_group 0;" ::: "memory");
        }
        __syncthreads();

        const uint32_t bufA = sb + (uint32_t)(c & 1) * 32768u;
        const uint32_t bufB = bufA + 16384u;
#pragma unroll
        for (int ks = 0; ks < 4; ks++) {
            uint32_t a[4][4];
#pragma unroll
            for (int i = 0; i < 4; i++) {
                uint32_t addr = bufA + SW128((uint32_t)((aRow + i * 16) * 128 + ks * 32 + aColB));
                asm volatile("ldmatrix.sync.aligned.m8n8.x4.shared.b16 {%0,%1,%2,%3}, [%4];"
                    : "=r"(a[i][0]), "=r"(a[i][1]), "=r"(a[i][2]), "=r"(a[i][3]) : "r"(addr));
            }
            uint32_t b[4][2];
#pragma unroll
            for (int j = 0; j < 4; j++) {
                uint32_t addr = bufB + SW128((uint32_t)((bRow + j * 8) * 128 + ks * 32 + bColB));
                asm volatile("ldmatrix.sync.aligned.m8n8.x2.shared.b16 {%0,%1}, [%2];"
                    : "=r"(b[j][0]), "=r"(b[j][1]) : "r"(addr));
            }
#pragma unroll
            for (int i = 0; i < 4; i++)
#pragma unroll
                for (int j = 0; j < 4; j++)
                    asm volatile(
                        "mma.sync.aligned.m16n8k16.row.col.f32.bf16.bf16.f32 "
                        "{%0,%1,%2,%3}, {%4,%5,%6,%7}, {%8,%9}, {%0,%1,%2,%3};"
                        : "+f"(acc[i][j][0]), "+f"(acc[i][j][1]),
                          "+f"(acc[i][j][2]), "+f"(acc[i][j][3])
                        : "r"(a[i][0]), "r"(a[i][1]), "r"(a[i][2]), "r"(a[i][3]),
                          "r"(b[j][0]), "r"(b[j][1]));
        }
        __syncthreads();
    }

    // ---- epilogue: write accumulators ----
    const int group = lane >> 2, tid4 = lane & 3;
#pragma unroll
    for (int i = 0; i < 4; i++) {
#pragma unroll
        for (int j = 0; j < 4; j++) {
            const int cn = wn + j * 8 + tid4 * 2;
            if (cn >= Ncols) continue;
            const long gm = m0 + wm + i * 16 + group;
            const long gn = n0 + cn;
            store_elem<MODE>(out, bias, z, gm,     gn,     acc[i][j][0]);
            store_elem<MODE>(out, bias, z, gm,     gn + 1, acc[i][j][1]);
            store_elem<MODE>(out, bias, z, gm + 8, gn,     acc[i][j][2]);
            store_elem<MODE>(out, bias, z, gm + 8, gn + 1, acc[i][j][3]);
        }
    }
}

// ---------------- prep kernels ----------------------------------------------
__global__ __launch_bounds__(256) void conv_A(const float* __restrict__ in,
                                              __nv_bfloat16* __restrict__ out, long n) {
    long i = (long)blockIdx.x * 256 + threadIdx.x;
    if (i >= n) return;
    float v = in[i];
    __nv_bfloat16 hi = __float2bfloat16(v);
    __nv_bfloat16 lo = __float2bfloat16(v - __bfloat162float(hi));
    out[3 * i] = hi; out[3 * i + 1] = hi; out[3 * i + 2] = lo;
}
__global__ __launch_bounds__(256) void conv_B(const float* __restrict__ in,
                                              __nv_bfloat16* __restrict__ out, long n) {
    long i = (long)blockIdx.x * 256 + threadIdx.x;
    if (i >= n) return;
    float v = in[i];
    __nv_bfloat16 hi = __float2bfloat16(v);
    __nv_bfloat16 lo = __float2bfloat16(v - __bfloat162float(hi));
    out[3 * i] = hi; out[3 * i + 1] = lo; out[3 * i + 2] = hi;
}
__global__ __launch_bounds__(256) void pad_qk(__nv_bfloat16* __restrict__ q3,
                                              __nv_bfloat16* __restrict__ k3) {
    long i = (long)blockIdx.x * 256 + threadIdx.x;   // BH*NSEQ*32
    long row = i >> 5; int c = (int)(i & 31);
    long off = row * KQK + 288 + c;
    q3[off] = __float2bfloat16(0.f);
    k3[off] = __float2bfloat16(0.f);
}

// softmax over S rows + write split P3 (A pattern [hi,hi,lo])
__global__ __launch_bounds__(256)
void softmax_split(const float* __restrict__ S, __nv_bfloat16* __restrict__ P3) {
    const long row = blockIdx.x;
    const float* p = S + row * (long)NSEQ;
    __nv_bfloat16* o = P3 + row * (long)KPV;
    const int t = threadIdx.x;
    __shared__ float red[8];

    float m = -3.0e38f;
    for (int i = t; i < NSEQ; i += 256) m = fmaxf(m, p[i]);
#pragma unroll
    for (int ofs = 16; ofs; ofs >>= 1) m = fmaxf(m, __shfl_xor_sync(~0u, m, ofs));
    if ((t & 31) == 0) red[t >> 5] = m;
    __syncthreads();
    float mx = red[0];
#pragma unroll
    for (int w = 1; w < 8; w++) mx = fmaxf(mx, red[w]);
    __syncthreads();

    float s = 0.f;
    float ebuf[8];
#pragma unroll
    for (int ii = 0; ii < 8; ii++) {
        float e = __expf(p[t + ii * 256] - mx);
        ebuf[ii] = e;
        s += e;
    }
#pragma unroll
    for (int ofs = 16; ofs; ofs >>= 1) s += __shfl_xor_sync(~0u, s, ofs);
    if ((t & 31) == 0) red[t >> 5] = s;
    __syncthreads();
    float tot = red[0];
#pragma unroll
    for (int w = 1; w < 8; w++) tot += red[w];
    const float inv = 1.0f / tot;

#pragma unroll
    for (int ii = 0; ii < 8; ii++) {
        const int i = t + ii * 256;
        float v = ebuf[ii] * inv;
        __nv_bfloat16 hi = __float2bfloat16(v);
        __nv_bfloat16 lo = __float2bfloat16(v - __bfloat162float(hi));
        o[3 * i] = hi; o[3 * i + 1] = hi; o[3 * i + 2] = lo;
    }
}

// ---------------- launcher ---------------------------------------------------
extern "C" void kernel_launch(void* const* d_in, const int* in_sizes, int n_in,
                              void* d_out, int out_size)
{
    const float* x  = (const float*)d_in[0];
    const float* Wq = (const float*)d_in[1];
    const float* bq = (const float*)d_in[2];
    const float* Wk = (const float*)d_in[3];
    const float* bk = (const float*)d_in[4];
    const float* Wv = (const float*)d_in[5];
    const float* bv = (const float*)d_in[6];
    const float* Wo = (const float*)d_in[7];
    const float* bo = (const float*)d_in[8];
    float* out = (float*)d_out;

    __nv_bfloat16 *x3, *wq3, *wk3, *wv3, *wo3, *q3, *k3, *v3, *p3, *ao3;
    float* S;
    cudaGetSymbolAddress((void**)&x3,  g_x3);
    cudaGetSymbolAddress((void**)&wq3, g_wq3);
    cudaGetSymbolAddress((void**)&wk3, g_wk3);
    cudaGetSymbolAddress((void**)&wv3, g_wv3);
    cudaGetSymbolAddress((void**)&wo3, g_wo3);
    cudaGetSymbolAddress((void**)&q3,  g_q3);
    cudaGetSymbolAddress((void**)&k3,  g_k3);
    cudaGetSymbolAddress((void**)&v3,  g_v3);
    cudaGetSymbolAddress((void**)&S,   g_S);
    cudaGetSymbolAddress((void**)&p3,  g_p3);
    cudaGetSymbolAddress((void**)&ao3, g_ao3);

    cudaFuncSetAttribute(mma_gemm<0>, cudaFuncAttributeMaxDynamicSharedMemorySize, SMEM_TOTAL);
    cudaFuncSetAttribute(mma_gemm<1>, cudaFuncAttributeMaxDynamicSharedMemorySize, SMEM_TOTAL);
    cudaFuncSetAttribute(mma_gemm<2>, cudaFuncAttributeMaxDynamicSharedMemorySize, SMEM_TOTAL);
    cudaFuncSetAttribute(mma_gemm<3>, cudaFuncAttributeMaxDynamicSharedMemorySize, SMEM_TOTAL);
    cudaFuncSetAttribute(mma_gemm<4>, cudaFuncAttributeMaxDynamicSharedMemorySize, SMEM_TOTAL);
    cudaFuncSetAttribute(mma_gemm<5>, cudaFuncAttributeMaxDynamicSharedMemorySize, SMEM_TOTAL);

    // prep: split-convert inputs
    conv_A<<<(MR * EMB + 255) / 256, 256>>>(x, x3, (long)MR * EMB);
    conv_B<<<(EMB * EMB + 255) / 256, 256>>>(Wq, wq3, (long)EMB * EMB);
    conv_B<<<(EMB * EMB + 255) / 256, 256>>>(Wk, wk3, (long)EMB * EMB);
    conv_B<<<(EMB * EMB + 255) / 256, 256>>>(Wv, wv3, (long)EMB * EMB);
    conv_B<<<(EMB * EMB + 255) / 256, 256>>>(Wo, wo3, (long)EMB * EMB);
    pad_qk<<<(BH * NSEQ * 32) / 256, 256>>>(q3, k3);

    // projections: q3/k3/v3 produced pre-split in attention layouts
    dim3 gp(EMB / 128, MR / 128, 1);
    mma_gemm<0><<<gp, 256, SMEM_TOTAL>>>(x3, wq3, bq, q3, K3, K3, K3 / 64, 128, 128, 0, 0);
    mma_gemm<1><<<gp, 256, SMEM_TOTAL>>>(x3, wk3, bk, k3, K3, K3, K3 / 64, 128, 128, 0, 0);
    mma_gemm<2><<<gp, 256, SMEM_TOTAL>>>(x3, wv3, bv, v3, K3, K3, K3 / 64, 128, 128, 0, 0);

    // scores S = Qs @ K^T (scale already folded into Q)
    dim3 gs(NSEQ / 128, NSEQ / 128, BH);
    mma_gemm<3><<<gs, 256, SMEM_TOTAL>>>(q3, k3, nullptr, S, KQK, KQK, KQK / 64, 128, 128,
                                         (long)NSEQ * KQK, (long)NSEQ * KQK);

    // softmax + split into P3
    softmax_split<<<BH * NSEQ, 256>>>(S, p3);

    // O = P @ V -> ao3 (pre-split for final projection)
    dim3 go(1, NSEQ / 128, BH);
    mma_gemm<4><<<go, 256, SMEM_TOTAL>>>(p3, v3, nullptr, ao3, KPV, KPV, KPV / 64, 96, 96,
                                         (long)NSEQ * KPV, (long)HD * KPV);

    // final projection
    dim3 gf(EMB / 128, MR / 128, 1);
    mma_gemm<5><<<gf, 256, SMEM_TOTAL>>>(ao3, wo3, bo, out, K3, K3, K3 / 64, 128, 128, 0, 0);
}

// round 4
// speedup vs baseline: 6.2916x; 1.7162x over previous
#include <cuda_runtime.h>
#include <cuda_bf16.h>
#include <cstdint>

#define EMB  768
#define NH   8
#define HD   96
#define NB   4
#define NSEQ 2048
#define BH   32            // NB*NH
#define MR   8192          // NB*NSEQ
#define K3   2304          // 3*EMB   (split-interleaved K)
#define KQK  320           // 3*HD=288 padded to 320 (5 chunks of 64)

// ---------------- scratch (device globals; no allocation allowed) -----------
__device__ __nv_bfloat16 g_x3 [(long)MR * K3];
__device__ __nv_bfloat16 g_wq3[(long)EMB * K3];
__device__ __nv_bfloat16 g_wk3[(long)EMB * K3];
__device__ __nv_bfloat16 g_wv3[(long)EMB * K3];
__device__ __nv_bfloat16 g_wo3[(long)EMB * K3];
__device__ __nv_bfloat16 g_q3 [(long)BH * NSEQ * KQK];
__device__ __nv_bfloat16 g_k3 [(long)BH * NSEQ * KQK];
__device__ __nv_bfloat16 g_vh [(long)BH * HD * NSEQ];   // V hi plane [bh][d][n]
__device__ __nv_bfloat16 g_vl [(long)BH * HD * NSEQ];   // V lo plane
__device__ __nv_bfloat16 g_ao3[(long)MR * K3];

// ---------------- helpers ----------------------------------------------------
#define SW128(o) ((o) ^ (((o) >> 3) & 0x70))

__device__ __forceinline__ uint32_t smem_u32(const void* p) {
    uint32_t a;
    asm("{ .reg .u64 t; cvta.to.shared.u64 t, %1; cvt.u32.u64 %0, t; }" : "=r"(a) : "l"(p));
    return a;
}
__device__ __forceinline__ void cp16(uint32_t dst, const void* src, uint32_t sz) {
    asm volatile("cp.async.cg.shared.global [%0], [%1], 16, %2;"
                 :: "r"(dst), "l"(src), "r"(sz) : "memory");
}
__device__ __forceinline__ float ex2(float x) {
    float r; asm("ex2.approx.f32 %0, %1;" : "=f"(r) : "f"(x)); return r;
}
__device__ __forceinline__ uint32_t packbf(float lo, float hi) {
    uint32_t r; asm("cvt.rn.bf16x2.f32 %0, %1, %2;" : "=r"(r) : "f"(hi), "f"(lo)); return r;
}
#define MMA_BF16(C, A, B)                                                        \
    asm volatile("mma.sync.aligned.m16n8k16.row.col.f32.bf16.bf16.f32 "          \
        "{%0,%1,%2,%3}, {%4,%5,%6,%7}, {%8,%9}, {%0,%1,%2,%3};"                  \
        : "+f"((C)[0]), "+f"((C)[1]), "+f"((C)[2]), "+f"((C)[3])                 \
        : "r"((A)[0]), "r"((A)[1]), "r"((A)[2]), "r"((A)[3]),                    \
          "r"((B)[0]), "r"((B)[1]))

// ---------------- epilogue element store (projection GEMMs) ------------------
// MODE: 0=Qproj 1=Kproj 2=Vproj(planes) 5=Out
template<int MODE>
__device__ __forceinline__ void store_elem(void* out, void* out2, const float* bias,
                                           int z, long m, long n, float v)
{
    if (MODE == 5) {
        ((float*)out)[m * (long)EMB + n] = v + bias[n];
    } else {
        v += bias[n];
        if (MODE == 0) v *= 0.14724445f;   // (1/sqrt(96)) * log2(e)
        const int h = (int)n / HD, dd = (int)n % HD;
        const int bb = (int)(m / NSEQ), ns = (int)(m % NSEQ);
        const int bh = bb * NH + h;
        __nv_bfloat16 hi = __float2bfloat16(v);
        __nv_bfloat16 lo = __float2bfloat16(v - __bfloat162float(hi));
        if (MODE == 2) {                   // V planes [bh][d][n]
            const long idx = ((long)bh * HD + dd) * NSEQ + ns;
            ((__nv_bfloat16*)out)[idx]  = hi;
            ((__nv_bfloat16*)out2)[idx] = lo;
        } else {
            __nv_bfloat16* o = (__nv_bfloat16*)out;
            const long base = ((long)bh * NSEQ + ns) * KQK + 3 * dd;
            if (MODE == 0) { o[base] = hi; o[base + 1] = hi; o[base + 2] = lo; } // A pat
            else           { o[base] = hi; o[base + 1] = lo; o[base + 2] = hi; } // B pat
        }
    }
}

// ---------------- HMMA (mma.sync) GEMM ---------------------------------------
#define SMEM_GEMM 65536

template<int MODE>
__global__ __launch_bounds__(256)
void mma_gemm(const __nv_bfloat16* __restrict__ A, const __nv_bfloat16* __restrict__ B,
              const float* __restrict__ bias, void* __restrict__ out, void* __restrict__ out2,
              int lda, int ldb, int Kc)
{
    extern __shared__ char smem[];
    const uint32_t sb = smem_u32(smem);
    const int tid = threadIdx.x;
    const int wid = tid >> 5, lane = tid & 31;
    const int z = blockIdx.z;
    const long m0 = (long)blockIdx.y * 128;
    const long n0 = (long)blockIdx.x * 128;
    A += m0 * lda;
    B += n0 * ldb;

    const int wm = (wid & 1) * 64;
    const int wn = (wid >> 1) * 32;

    float acc[4][4][4];
#pragma unroll
    for (int i = 0; i < 4; i++)
#pragma unroll
        for (int j = 0; j < 4; j++)
#pragma unroll
            for (int c = 0; c < 4; c++) acc[i][j][c] = 0.f;

    const int l16   = lane & 15;
    const int aRow  = wm + l16;
    const int aColB = (lane >> 4) * 16;
    const int bRow  = wn + (l16 & 7);
    const int bColB = ((l16 >> 3) & 1) * 16;

    auto stage = [&](int c) {
        const long k0 = (long)c * 64;
        const uint32_t bufA = sb + (uint32_t)(c & 1) * 32768u;
        const uint32_t bufB = bufA + 16384u;
#pragma unroll
        for (int i = 0; i < 4; i++) {
            int v = tid + i * 256;
            int row = v >> 3, c16 = v & 7;
            uint32_t off = SW128((uint32_t)(row * 128 + c16 * 16));
            cp16(bufA + off, A + (long)row * lda + k0 + c16 * 8, 16u);
            cp16(bufB + off, B + (long)row * ldb + k0 + c16 * 8, 16u);
        }
        asm volatile("cp.async.commit_group;" ::: "memory");
    };

    stage(0);
    for (int c = 0; c < Kc; c++) {
        if (c + 1 < Kc) {
            stage(c + 1);
            asm volatile("cp.async.wait_group 1;" ::: "memory");
        } else {
            asm volatile("cp.async.wait_group 0;" ::: "memory");
        }
        __syncthreads();

        const uint32_t bufA = sb + (uint32_t)(c & 1) * 32768u;
        const uint32_t bufB = bufA + 16384u;
#pragma unroll
        for (int ks = 0; ks < 4; ks++) {
            uint32_t a[4][4];
#pragma unroll
            for (int i = 0; i < 4; i++) {
                uint32_t addr = bufA + SW128((uint32_t)((aRow + i * 16) * 128 + ks * 32 + aColB));
                asm volatile("ldmatrix.sync.aligned.m8n8.x4.shared.b16 {%0,%1,%2,%3}, [%4];"
                    : "=r"(a[i][0]), "=r"(a[i][1]), "=r"(a[i][2]), "=r"(a[i][3]) : "r"(addr));
            }
            uint32_t b[4][2];
#pragma unroll
            for (int j = 0; j < 4; j++) {
                uint32_t addr = bufB + SW128((uint32_t)((bRow + j * 8) * 128 + ks * 32 + bColB));
                asm volatile("ldmatrix.sync.aligned.m8n8.x2.shared.b16 {%0,%1}, [%2];"
                    : "=r"(b[j][0]), "=r"(b[j][1]) : "r"(addr));
            }
#pragma unroll
            for (int i = 0; i < 4; i++)
#pragma unroll
                for (int j = 0; j < 4; j++)
                    MMA_BF16(acc[i][j], a[i], b[j]);
        }
        __syncthreads();
    }

    const int group = lane >> 2, tid4 = lane & 3;
#pragma unroll
    for (int i = 0; i < 4; i++) {
#pragma unroll
        for (int j = 0; j < 4; j++) {
            const long gm = m0 + wm + i * 16 + group;
            const long gn = n0 + wn + j * 8 + tid4 * 2;
            store_elem<MODE>(out, out2, bias, z, gm,     gn,     acc[i][j][0]);
            store_elem<MODE>(out, out2, bias, z, gm,     gn + 1, acc[i][j][1]);
            store_elem<MODE>(out, out2, bias, z, gm + 8, gn,     acc[i][j][2]);
            store_elem<MODE>(out, out2, bias, z, gm + 8, gn + 1, acc[i][j][3]);
        }
    }
}

// ---------------- fused flash attention --------------------------------------
// Per CTA: one (bh, 128-query tile). 8 warps x 16 rows. Streams 64-key tiles.
// SMEM: Q 5x16KB resident | K 2x(5x8KB) | V 2x(hi 12KB + lo 12KB) = 208KB
#define QSM 0
#define KSM 81920
#define VSM 163840
#define SMEM_FA 212992

__global__ __launch_bounds__(256)
void flash_attn(const __nv_bfloat16* __restrict__ q3,
                const __nv_bfloat16* __restrict__ k3,
                const __nv_bfloat16* __restrict__ vh,
                const __nv_bfloat16* __restrict__ vl,
                __nv_bfloat16* __restrict__ ao3)
{
    extern __shared__ char smem[];
    const uint32_t sb = smem_u32(smem);
    const int tid = threadIdx.x, wid = tid >> 5, lane = tid & 31;
    const int bh = blockIdx.y;
    const long q0 = (long)blockIdx.x * 128;
    const __nv_bfloat16* qp  = q3 + ((long)bh * NSEQ + q0) * KQK;
    const __nv_bfloat16* kp  = k3 + (long)bh * NSEQ * KQK;
    const __nv_bfloat16* vhp = vh + (long)bh * HD * NSEQ;
    const __nv_bfloat16* vlp = vl + (long)bh * HD * NSEQ;

    // Q tile: 5 chunks x (128 rows x 128B), loaded once
#pragma unroll
    for (int t = 0; t < 20; t++) {
        int i = tid + t * 256;                 // 5120 = 5*128*8
        int chunk = i >> 10, rem = i & 1023;
        int row = rem >> 3, c16 = rem & 7;
        cp16(sb + QSM + chunk * 16384 + SW128((uint32_t)(row * 128 + c16 * 16)),
             qp + (long)row * KQK + chunk * 64 + c16 * 8, 16u);
    }

    auto stageKV = [&](int it) {
        const int buf = it & 1;
        const long kb = (long)it * 64;
        // K tile: 5 chunks x (64 rows x 128B)
#pragma unroll
        for (int t = 0; t < 10; t++) {
            int i = tid + t * 256;             // 2560
            int chunk = i >> 9, rem = i & 511;
            int row = rem >> 3, c16 = rem & 7;
            cp16(sb + KSM + buf * 40960 + chunk * 8192 + SW128((uint32_t)(row * 128 + c16 * 16)),
                 kp + (kb + row) * KQK + chunk * 64 + c16 * 8, 16u);
        }
        // V planes: 96 rows x 128B each
#pragma unroll
        for (int t = 0; t < 6; t++) {
            int i = tid + t * 256;             // 1536
            int plane = i >= 768 ? 1 : 0;
            int rem = i - plane * 768;
            int row = rem >> 3, c16 = rem & 7;
            const __nv_bfloat16* src = plane ? vlp : vhp;
            cp16(sb + VSM + buf * 24576 + plane * 12288 + SW128((uint32_t)(row * 128 + c16 * 16)),
                 src + (long)row * NSEQ + kb + c16 * 8, 16u);
        }
        asm volatile("cp.async.commit_group;" ::: "memory");
    };

    stageKV(0);   // group0 = Q + tile0
    stageKV(1);   // group1

    float O[12][4];
#pragma unroll
    for (int n = 0; n < 12; n++)
#pragma unroll
        for (int c = 0; c < 4; c++) O[n][c] = 0.f;
    float mA = -1e30f, mB = -1e30f, lA = 0.f, lB = 0.f;

    const int l16 = lane & 15;
    const int aRow = wid * 16 + l16;
    const int aColB = (lane >> 4) * 16;
    const int bRow8 = l16 & 7;
    const int bColB = ((l16 >> 3) & 1) * 16;

    for (int it = 0; it < 32; it++) {
        const int buf = it & 1;
        if (it >= 30) { asm volatile("cp.async.wait_group 0;" ::: "memory"); }
        else          { asm volatile("cp.async.wait_group 1;" ::: "memory"); }
        __syncthreads();

        // ---- S = Qs @ K^T (5 chunks of 64, split-interleaved) ----
        float S[8][4];
#pragma unroll
        for (int n = 0; n < 8; n++)
#pragma unroll
            for (int c = 0; c < 4; c++) S[n][c] = 0.f;

        const uint32_t kbase = sb + KSM + buf * 40960;
#pragma unroll
        for (int cc = 0; cc < 5; cc++) {
#pragma unroll
            for (int ks = 0; ks < 4; ks++) {
                uint32_t a[4];
                uint32_t addr = sb + QSM + cc * 16384 +
                                SW128((uint32_t)(aRow * 128 + ks * 32 + aColB));
                asm volatile("ldmatrix.sync.aligned.m8n8.x4.shared.b16 {%0,%1,%2,%3}, [%4];"
                    : "=r"(a[0]), "=r"(a[1]), "=r"(a[2]), "=r"(a[3]) : "r"(addr));
#pragma unroll
                for (int nt = 0; nt < 8; nt++) {
                    uint32_t b[2];
                    uint32_t baddr = kbase + cc * 8192 +
                        SW128((uint32_t)((nt * 8 + bRow8) * 128 + ks * 32 + bColB));
                    asm volatile("ldmatrix.sync.aligned.m8n8.x2.shared.b16 {%0,%1}, [%2];"
                        : "=r"(b[0]), "=r"(b[1]) : "r"(baddr));
                    MMA_BF16(S[nt], a, b);
                }
            }
        }

        // ---- online softmax (log2 domain; scale*log2e folded into Q) ----
        float mxA = -1e30f, mxB = -1e30f;
#pragma unroll
        for (int nt = 0; nt < 8; nt++) {
            mxA = fmaxf(mxA, fmaxf(S[nt][0], S[nt][1]));
            mxB = fmaxf(mxB, fmaxf(S[nt][2], S[nt][3]));
        }
        mxA = fmaxf(mxA, __shfl_xor_sync(~0u, mxA, 1));
        mxA = fmaxf(mxA, __shfl_xor_sync(~0u, mxA, 2));
        mxB = fmaxf(mxB, __shfl_xor_sync(~0u, mxB, 1));
        mxB = fmaxf(mxB, __shfl_xor_sync(~0u, mxB, 2));
        const float mnA = fmaxf(mA, mxA), mnB = fmaxf(mB, mxB);
        const float scA = ex2(mA - mnA), scB = ex2(mB - mnB);
        mA = mnA; mB = mnB;

        float sumA = 0.f, sumB = 0.f;
#pragma unroll
        for (int nt = 0; nt < 8; nt++) {
            S[nt][0] = ex2(S[nt][0] - mnA);
            S[nt][1] = ex2(S[nt][1] - mnA);
            S[nt][2] = ex2(S[nt][2] - mnB);
            S[nt][3] = ex2(S[nt][3] - mnB);
            sumA += S[nt][0] + S[nt][1];
            sumB += S[nt][2] + S[nt][3];
        }
        sumA += __shfl_xor_sync(~0u, sumA, 1);
        sumA += __shfl_xor_sync(~0u, sumA, 2);
        sumB += __shfl_xor_sync(~0u, sumB, 1);
        sumB += __shfl_xor_sync(~0u, sumB, 2);
        lA = lA * scA + sumA;
        lB = lB * scB + sumB;
#pragma unroll
        for (int nt = 0; nt < 12; nt++) {
            O[nt][0] *= scA; O[nt][1] *= scA;
            O[nt][2] *= scB; O[nt][3] *= scB;
        }

        // ---- pack P into A-fragments (hi + lo split) ----
        uint32_t aHi[4][4], aLo[4][4];
#pragma unroll
        for (int ks = 0; ks < 4; ks++) {
#pragma unroll
            for (int q = 0; q < 4; q++) {
                const int nt = 2 * ks + (q >> 1);
                const float p0 = S[nt][(q & 1) * 2], p1 = S[nt][(q & 1) * 2 + 1];
                const uint32_t h = packbf(p0, p1);
                aHi[ks][q] = h;
                const float h0 = __uint_as_float(h << 16);
                const float h1 = __uint_as_float(h & 0xFFFF0000u);
                aLo[ks][q] = packbf(p0 - h0, p1 - h1);
            }
        }

        // ---- O += Phi@Vhi + Plo@Vhi + Phi@Vlo ----
        const uint32_t vhb = sb + VSM + buf * 24576, vlb = vhb + 12288;
#pragma unroll
        for (int ks = 0; ks < 4; ks++) {
#pragma unroll
            for (int nt = 0; nt < 12; nt++) {
                const uint32_t soff =
                    SW128((uint32_t)((nt * 8 + bRow8) * 128 + ks * 32 + bColB));
                uint32_t b[2];
                asm volatile("ldmatrix.sync.aligned.m8n8.x2.shared.b16 {%0,%1}, [%2];"
                    : "=r"(b[0]), "=r"(b[1]) : "r"(vhb + soff));
                MMA_BF16(O[nt], aHi[ks], b);
                MMA_BF16(O[nt], aLo[ks], b);
                asm volatile("ldmatrix.sync.aligned.m8n8.x2.shared.b16 {%0,%1}, [%2];"
                    : "=r"(b[0]), "=r"(b[1]) : "r"(vlb + soff));
                MMA_BF16(O[nt], aHi[ks], b);
            }
        }
        __syncthreads();
        if (it + 2 < 32) stageKV(it + 2);
    }

    // ---- epilogue: O/l, split-store into ao3 (A pattern) ----
    const float invA = 1.f / lA, invB = 1.f / lB;
    const int bb = bh >> 3, h = bh & 7;
    const long mGA = q0 + wid * 16 + (lane >> 2);
    auto stA = [&](long base, float v) {
        __nv_bfloat16 hv = __float2bfloat16(v);
        ao3[base] = hv; ao3[base + 1] = hv;
        ao3[base + 2] = __float2bfloat16(v - __bfloat162float(hv));
    };
#pragma unroll
    for (int nt = 0; nt < 12; nt++) {
        const int dd = nt * 8 + (lane & 3) * 2;
        const long baseA = ((long)bb * NSEQ + mGA) * K3 + 3L * (h * HD + dd);
        const long baseB = baseA + 8L * K3;
        stA(baseA,     O[nt][0] * invA);
        stA(baseA + 3, O[nt][1] * invA);
        stA(baseB,     O[nt][2] * invB);
        stA(baseB + 3, O[nt][3] * invB);
    }
}

// ---------------- prep kernels ----------------------------------------------
__global__ __launch_bounds__(256) void conv_A(const float* __restrict__ in,
                                              __nv_bfloat16* __restrict__ out, long n) {
    long i = (long)blockIdx.x * 256 + threadIdx.x;
    if (i >= n) return;
    float v = in[i];
    __nv_bfloat16 hi = __float2bfloat16(v);
    __nv_bfloat16 lo = __float2bfloat16(v - __bfloat162float(hi));
    out[3 * i] = hi; out[3 * i + 1] = hi; out[3 * i + 2] = lo;
}
__global__ __launch_bounds__(256) void conv_B(const float* __restrict__ in,
                                              __nv_bfloat16* __restrict__ out, long n) {
    long i = (long)blockIdx.x * 256 + threadIdx.x;
    if (i >= n) return;
    float v = in[i];
    __nv_bfloat16 hi = __float2bfloat16(v);
    __nv_bfloat16 lo = __float2bfloat16(v - __bfloat162float(hi));
    out[3 * i] = hi; out[3 * i + 1] = lo; out[3 * i + 2] = hi;
}
__global__ __launch_bounds__(256) void pad_qk(__nv_bfloat16* __restrict__ q3,
                                              __nv_bfloat16* __restrict__ k3) {
    long i = (long)blockIdx.x * 256 + threadIdx.x;   // BH*NSEQ*32
    long row = i >> 5; int c = (int)(i & 31);
    long off = row * KQK + 288 + c;
    q3[off] = __float2bfloat16(0.f);
    k3[off] = __float2bfloat16(0.f);
}

// ---------------- launcher ---------------------------------------------------
extern "C" void kernel_launch(void* const* d_in, const int* in_sizes, int n_in,
                              void* d_out, int out_size)
{
    const float* x  = (const float*)d_in[0];
    const float* Wq = (const float*)d_in[1];
    const float* bq = (const float*)d_in[2];
    const float* Wk = (const float*)d_in[3];
    const float* bk = (const float*)d_in[4];
    const float* Wv = (const float*)d_in[5];
    const float* bv = (const float*)d_in[6];
    const float* Wo = (const float*)d_in[7];
    const float* bo = (const float*)d_in[8];
    float* out = (float*)d_out;

    __nv_bfloat16 *x3, *wq3, *wk3, *wv3, *wo3, *q3, *k3, *vh, *vl, *ao3;
    cudaGetSymbolAddress((void**)&x3,  g_x3);
    cudaGetSymbolAddress((void**)&wq3, g_wq3);
    cudaGetSymbolAddress((void**)&wk3, g_wk3);
    cudaGetSymbolAddress((void**)&wv3, g_wv3);
    cudaGetSymbolAddress((void**)&wo3, g_wo3);
    cudaGetSymbolAddress((void**)&q3,  g_q3);
    cudaGetSymbolAddress((void**)&k3,  g_k3);
    cudaGetSymbolAddress((void**)&vh,  g_vh);
    cudaGetSymbolAddress((void**)&vl,  g_vl);
    cudaGetSymbolAddress((void**)&ao3, g_ao3);

    cudaFuncSetAttribute(mma_gemm<0>, cudaFuncAttributeMaxDynamicSharedMemorySize, SMEM_GEMM);
    cudaFuncSetAttribute(mma_gemm<1>, cudaFuncAttributeMaxDynamicSharedMemorySize, SMEM_GEMM);
    cudaFuncSetAttribute(mma_gemm<2>, cudaFuncAttributeMaxDynamicSharedMemorySize, SMEM_GEMM);
    cudaFuncSetAttribute(mma_gemm<5>, cudaFuncAttributeMaxDynamicSharedMemorySize, SMEM_GEMM);
    cudaFuncSetAttribute(flash_attn,  cudaFuncAttributeMaxDynamicSharedMemorySize, SMEM_FA);

    // prep: split-convert inputs
    conv_A<<<(MR * EMB + 255) / 256, 256>>>(x, x3, (long)MR * EMB);
    conv_B<<<(EMB * EMB + 255) / 256, 256>>>(Wq, wq3, (long)EMB * EMB);
    conv_B<<<(EMB * EMB + 255) / 256, 256>>>(Wk, wk3, (long)EMB * EMB);
    conv_B<<<(EMB * EMB + 255) / 256, 256>>>(Wv, wv3, (long)EMB * EMB);
    conv_B<<<(EMB * EMB + 255) / 256, 256>>>(Wo, wo3, (long)EMB * EMB);
    pad_qk<<<(BH * NSEQ * 32) / 256, 256>>>(q3, k3);

    // projections (Q scale includes log2e for exp2-domain softmax)
    dim3 gp(EMB / 128, MR / 128, 1);
    mma_gemm<0><<<gp, 256, SMEM_GEMM>>>(x3, wq3, bq, q3, nullptr, K3, K3, K3 / 64);
    mma_gemm<1><<<gp, 256, SMEM_GEMM>>>(x3, wk3, bk, k3, nullptr, K3, K3, K3 / 64);
    mma_gemm<2><<<gp, 256, SMEM_GEMM>>>(x3, wv3, bv, vh, vl, K3, K3, K3 / 64);

    // fused attention -> ao3 (pre-split for final projection)
    flash_attn<<<dim3(NSEQ / 128, BH), 256, SMEM_FA>>>(q3, k3, vh, vl, ao3);

    // final projection
    dim3 gf(EMB / 128, MR / 128, 1);
    mma_gemm<5><<<gf, 256, SMEM_GEMM>>>(ao3, wo3, bo, out, nullptr, K3, K3, K3 / 64);
}